// round 1
// baseline (speedup 1.0000x reference)
#include <cuda_runtime.h>
#include <math.h>

// ---------------- scratch (static, no allocations) ----------------
#define MAXN  65536
#define TABK  16384
#define TABXMAX 16.0f

__device__ float        g_Ai[MAXN * 8];      // per-node atom features
__device__ unsigned int g_cnt[MAXN];         // per-node edge counts
__device__ float4       g_tab[TABK];         // gates(length) table, PATH_NORM folded

__device__ __forceinline__ float silu_f(float x) {
    return x / (1.0f + __expf(-x));
}

// ---------------- per-node atom MLP: emb_table[A] -> 64 -> 8 ----------------
__global__ void node_kernel(const float* __restrict__ emb_table,
                            const int*   __restrict__ A,
                            const float* __restrict__ w1, const float* __restrict__ b1,
                            const float* __restrict__ w2, const float* __restrict__ b2,
                            int N)
{
    int n = blockIdx.x * blockDim.x + threadIdx.x;
    if (n >= N) return;
    g_cnt[n] = 0u;                       // zero counts for the edge pass

    int a = A[n];
    float e[16];
#pragma unroll
    for (int k = 0; k < 16; k++) e[k] = __ldg(emb_table + a * 16 + k);

    float h[64];
#pragma unroll
    for (int j = 0; j < 64; j++) {
        float acc = __ldg(b1 + j);
#pragma unroll
        for (int k = 0; k < 16; k++) acc += e[k] * __ldg(w1 + k * 64 + j);
        h[j] = silu_f(acc);
    }
#pragma unroll
    for (int m = 0; m < 8; m++) {
        float acc = __ldg(b2 + m);
#pragma unroll
        for (int j = 0; j < 64; j++) acc += h[j] * __ldg(w2 + j * 8 + m);
        g_Ai[n * 8 + m] = acc;
    }
}

// ---------------- gate table: gates(length) for paths {0,3,9}, *PATH_NORM ----------------
__global__ void table_kernel(const float* __restrict__ fw1, const float* __restrict__ fb1,
                             const float* __restrict__ fw2, const float* __restrict__ fb2,
                             const float* __restrict__ fw3, const float* __restrict__ fb3)
{
    int i = blockIdx.x * blockDim.x + threadIdx.x;
    if (i >= TABK) return;
    float x = (TABXMAX * (float)i) / (float)(TABK - 1);

    // soft_one_hot_gaussian(x, 0, 5, 16) * sqrt(16)
    const float step = 5.0f / 17.0f;
    float emb[16];
#pragma unroll
    for (int j = 0; j < 16; j++) {
        float v = 5.0f * (float)(j + 1) / 17.0f;
        float d = (x - v) / step;
        emb[j] = __expf(-d * d) * (4.0f / 1.12f);
    }

    float g1[64];
#pragma unroll
    for (int j = 0; j < 64; j++) {
        float acc = __ldg(fb1 + j);
#pragma unroll
        for (int k = 0; k < 16; k++) acc += emb[k] * __ldg(fw1 + k * 64 + j);
        g1[j] = silu_f(acc);
    }

    float g3a = __ldg(fb3 + 0), g3b = __ldg(fb3 + 3), g3c = __ldg(fb3 + 9);
#pragma unroll
    for (int j = 0; j < 64; j++) {
        float acc = __ldg(fb2 + j);
#pragma unroll
        for (int k = 0; k < 64; k++) acc += g1[k] * __ldg(fw2 + k * 64 + j);
        float s = silu_f(acc);
        g3a += s * __ldg(fw3 + j * 15 + 0);
        g3b += s * __ldg(fw3 + j * 15 + 3);
        g3c += s * __ldg(fw3 + j * 15 + 9);
    }
    const float PN = 0.125f; // 1/sqrt(MUL*MUL)
    g_tab[i] = make_float4(g3a * PN, g3b * PN, g3c * PN, 0.0f);
}

// ---------------- main edge kernel ----------------
__global__ void __launch_bounds__(256)
edge_kernel(const float* __restrict__ pos,
            const int*   __restrict__ esrc,
            const int*   __restrict__ edst,
            const float* __restrict__ shifts,
            const int*   __restrict__ batch,
            const float* __restrict__ cell,
            const float* __restrict__ tpw,
            float*       __restrict__ out,
            int E)
{
    // tp_w paths {0,3,9}: Wsm[l*1024 + (u*8+v)*16 + w]
    __shared__ float Wsm[3 * 64 * 16];
    {
        const int path0 = 0, path1 = 3, path2 = 9;
        for (int i = threadIdx.x; i < 1024; i += 256) {
            Wsm[i]        = tpw[path0 * 1024 + i];
            Wsm[1024 + i] = tpw[path1 * 1024 + i];
            Wsm[2048 + i] = tpw[path2 * 1024 + i];
        }
    }
    __syncthreads();

    int e = blockIdx.x * 256 + threadIdx.x;
    if (e >= E) return;

    int s0 = esrc[e];
    int d0 = edst[e];

    float dx = pos[d0 * 3 + 0] - pos[s0 * 3 + 0];
    float dy = pos[d0 * 3 + 1] - pos[s0 * 3 + 1];
    float dz = pos[d0 * 3 + 2] - pos[s0 * 3 + 2];

    float shx = shifts[e * 3 + 0];
    float shy = shifts[e * 3 + 1];
    float shz = shifts[e * 3 + 2];
    if (shx != 0.0f || shy != 0.0f || shz != 0.0f) {
        const float* c = cell + (size_t)batch[s0] * 9;
        dx += shx * c[0] + shy * c[3] + shz * c[6];
        dy += shx * c[1] + shy * c[4] + shz * c[7];
        dz += shx * c[2] + shy * c[5] + shz * c[8];
    }

    float len  = sqrtf(dx * dx + dy * dy + dz * dz);
    float rinv = 1.0f / fmaxf(len, 1e-8f);
    float nx = dx * rinv, ny = dy * rinv, nz = dz * rinv;

    // gate lookup (linear interp; table is exactly flat at the tail so clamping is exact)
    float t  = len * ((float)(TABK - 1) / TABXMAX);
    int   i0 = (int)t;
    i0 = i0 < (TABK - 2) ? i0 : (TABK - 2);
    float fr = t - (float)i0;
    float4 ga = g_tab[i0];
    float4 gb = g_tab[i0 + 1];
    float G0 = ga.x + fr * (gb.x - ga.x);
    float G1 = ga.y + fr * (gb.y - ga.y);
    float G2 = ga.z + fr * (gb.z - ga.z);

    // node features
    const float4* A4 = (const float4*)g_Ai;
    float4 aL = A4[s0 * 2 + 0], aH = A4[s0 * 2 + 1];
    float4 bL = A4[d0 * 2 + 0], bH = A4[d0 * 2 + 1];
    float a[8] = {aL.x, aL.y, aL.z, aL.w, aH.x, aH.y, aH.z, aH.w};
    float b[8] = {bL.x, bL.y, bL.z, bL.w, bH.x, bH.y, bH.z, bH.w};

    // s_l[w] = sum_{u,v} a[u] b[v] W_l[u,v,w]
    float s[48];
#pragma unroll
    for (int i = 0; i < 48; i++) s[i] = 0.0f;

#pragma unroll
    for (int u = 0; u < 8; u++) {
#pragma unroll
        for (int v = 0; v < 8; v++) {
            float p = a[u] * b[v];
            int base = (u * 8 + v) * 16;
#pragma unroll
            for (int l = 0; l < 3; l++) {
                const float4* w4 = (const float4*)(Wsm + l * 1024 + base);
#pragma unroll
                for (int q = 0; q < 4; q++) {
                    float4 w = w4[q];
                    s[l * 16 + q * 4 + 0] += p * w.x;
                    s[l * 16 + q * 4 + 1] += p * w.y;
                    s[l * 16 + q * 4 + 2] += p * w.z;
                    s[l * 16 + q * 4 + 3] += p * w.w;
                }
            }
        }
    }

    // fold gates
#pragma unroll
    for (int w = 0; w < 16; w++) {
        s[w]      *= G0;
        s[16 + w] *= G1;
        s[32 + w] *= G2;
    }

    // spherical harmonics
    const float SQ3   = 1.7320508075688772f;
    const float SQ15  = 3.872983346207417f;
    const float SQ5H  = 1.118033988749895f;   // sqrt(5)/2
    const float SQ15H = 1.9364916731037085f;  // sqrt(15)/2
    float Y1v[3] = {SQ3 * nx, SQ3 * ny, SQ3 * nz};
    float Y2v[5] = {SQ15 * nx * ny,
                    SQ15 * ny * nz,
                    SQ5H * (3.0f * nz * nz - 1.0f),
                    SQ15 * nx * nz,
                    SQ15H * (nx * nx - ny * ny)};

    float* row = out + (size_t)d0 * 144;

    // l=0: cols [0,16), Y0 = 1
#pragma unroll
    for (int j = 0; j < 16; j += 4) {
        atomicAdd((float4*)(row + j),
                  make_float4(s[j], s[j + 1], s[j + 2], s[j + 3]));
    }
    // l=1: cols [16,64), col = 16 + w*3 + i
#pragma unroll
    for (int j = 0; j < 48; j += 4) {
        float4 v = make_float4(
            s[16 + (j + 0) / 3] * Y1v[(j + 0) % 3],
            s[16 + (j + 1) / 3] * Y1v[(j + 1) % 3],
            s[16 + (j + 2) / 3] * Y1v[(j + 2) % 3],
            s[16 + (j + 3) / 3] * Y1v[(j + 3) % 3]);
        atomicAdd((float4*)(row + 16 + j), v);
    }
    // l=2: cols [64,144), col = 64 + w*5 + i
#pragma unroll
    for (int j = 0; j < 80; j += 4) {
        float4 v = make_float4(
            s[32 + (j + 0) / 5] * Y2v[(j + 0) % 5],
            s[32 + (j + 1) / 5] * Y2v[(j + 1) % 5],
            s[32 + (j + 2) / 5] * Y2v[(j + 2) % 5],
            s[32 + (j + 3) / 5] * Y2v[(j + 3) % 5]);
        atomicAdd((float4*)(row + 64 + j), v);
    }

    atomicAdd(&g_cnt[d0], 1u);
}

// ---------------- normalize: out[n] /= max(count[n],1) ----------------
__global__ void norm_kernel(float* __restrict__ out, int N)
{
    int i = blockIdx.x * blockDim.x + threadIdx.x;
    if (i >= N * 36) return;
    int n = i / 36;
    unsigned c = g_cnt[n];
    float inv = 1.0f / (float)(c > 0u ? c : 1u);
    float4* o = (float4*)out;
    float4 v = o[i];
    v.x *= inv; v.y *= inv; v.z *= inv; v.w *= inv;
    o[i] = v;
}

// ---------------- launch ----------------
extern "C" void kernel_launch(void* const* d_in, const int* in_sizes, int n_in,
                              void* d_out, int out_size)
{
    const float* pos    = (const float*)d_in[0];
    const int*   A      = (const int*)  d_in[1];
    const int*   batch  = (const int*)  d_in[2];
    const int*   esrc   = (const int*)  d_in[3];
    const int*   edst   = (const int*)  d_in[4];
    const float* shifts = (const float*)d_in[5];
    const float* cell   = (const float*)d_in[6];
    const float* embT   = (const float*)d_in[7];
    const float* aw1    = (const float*)d_in[8];
    const float* ab1    = (const float*)d_in[9];
    const float* aw2    = (const float*)d_in[10];
    const float* ab2    = (const float*)d_in[11];
    const float* fw1    = (const float*)d_in[12];
    const float* fb1    = (const float*)d_in[13];
    const float* fw2    = (const float*)d_in[14];
    const float* fb2    = (const float*)d_in[15];
    const float* fw3    = (const float*)d_in[16];
    const float* fb3    = (const float*)d_in[17];
    const float* tpw    = (const float*)d_in[18];

    int N = in_sizes[0] / 3;
    int E = in_sizes[3];
    float* out = (float*)d_out;

    cudaMemsetAsync(d_out, 0, (size_t)out_size * sizeof(float), 0);
    node_kernel<<<(N + 255) / 256, 256>>>(embT, A, aw1, ab1, aw2, ab2, N);
    table_kernel<<<TABK / 256, 256>>>(fw1, fb1, fw2, fb2, fw3, fb3);
    edge_kernel<<<(E + 255) / 256, 256>>>(pos, esrc, edst, shifts, batch, cell, tpw, out, E);
    norm_kernel<<<(N * 36 + 255) / 256, 256>>>(out, N);
}

// round 2
// speedup vs baseline: 1.7853x; 1.7853x over previous
#include <cuda_runtime.h>
#include <math.h>

// ---------------- scratch (static, no allocations) ----------------
#define MAXN  65536
#define TABK  16384
#define TABXMAX 16.0f

__device__ float        g_Ai[MAXN * 8];       // per-node atom features
__device__ float        g_T[MAXN * 72];       // scattered edge moments T[n, k(9), u(8)]
__device__ unsigned int g_cnt[MAXN];          // per-node edge counts
__device__ float4       g_tab[TABK];          // gates(length) table, PATH_NORM folded

__device__ __forceinline__ float silu_f(float x) {
    return x / (1.0f + __expf(-x));
}

// ---------------- per-node atom MLP: emb_table[A] -> 64 -> 8 ; also zero T,cnt ----------------
__global__ void node_kernel(const float* __restrict__ emb_table,
                            const int*   __restrict__ A,
                            const float* __restrict__ w1, const float* __restrict__ b1,
                            const float* __restrict__ w2, const float* __restrict__ b2,
                            int N)
{
    int n = blockIdx.x * blockDim.x + threadIdx.x;
    if (n >= N) return;
    g_cnt[n] = 0u;
    float4* T4 = (float4*)(g_T + (size_t)n * 72);
#pragma unroll
    for (int i = 0; i < 18; i++) T4[i] = make_float4(0.f, 0.f, 0.f, 0.f);

    int a = A[n];
    float e[16];
#pragma unroll
    for (int k = 0; k < 16; k++) e[k] = __ldg(emb_table + a * 16 + k);

    float h[64];
#pragma unroll
    for (int j = 0; j < 64; j++) {
        float acc = __ldg(b1 + j);
#pragma unroll
        for (int k = 0; k < 16; k++) acc += e[k] * __ldg(w1 + k * 64 + j);
        h[j] = silu_f(acc);
    }
#pragma unroll
    for (int m = 0; m < 8; m++) {
        float acc = __ldg(b2 + m);
#pragma unroll
        for (int j = 0; j < 64; j++) acc += h[j] * __ldg(w2 + j * 8 + m);
        g_Ai[n * 8 + m] = acc;
    }
}

// ---------------- gate table: gates(length) for paths {0,3,9}, *PATH_NORM ----------------
__global__ void table_kernel(const float* __restrict__ fw1, const float* __restrict__ fb1,
                             const float* __restrict__ fw2, const float* __restrict__ fb2,
                             const float* __restrict__ fw3, const float* __restrict__ fb3)
{
    int i = blockIdx.x * blockDim.x + threadIdx.x;
    if (i >= TABK) return;
    float x = (TABXMAX * (float)i) / (float)(TABK - 1);

    const float step = 5.0f / 17.0f;
    float emb[16];
#pragma unroll
    for (int j = 0; j < 16; j++) {
        float v = 5.0f * (float)(j + 1) / 17.0f;
        float d = (x - v) / step;
        emb[j] = __expf(-d * d) * (4.0f / 1.12f);
    }

    float g1[64];
#pragma unroll
    for (int j = 0; j < 64; j++) {
        float acc = __ldg(fb1 + j);
#pragma unroll
        for (int k = 0; k < 16; k++) acc += emb[k] * __ldg(fw1 + k * 64 + j);
        g1[j] = silu_f(acc);
    }

    float g3a = __ldg(fb3 + 0), g3b = __ldg(fb3 + 3), g3c = __ldg(fb3 + 9);
#pragma unroll
    for (int j = 0; j < 64; j++) {
        float acc = __ldg(fb2 + j);
#pragma unroll
        for (int k = 0; k < 64; k++) acc += g1[k] * __ldg(fw2 + k * 64 + j);
        float s = silu_f(acc);
        g3a += s * __ldg(fw3 + j * 15 + 0);
        g3b += s * __ldg(fw3 + j * 15 + 3);
        g3c += s * __ldg(fw3 + j * 15 + 9);
    }
    const float PN = 0.125f; // 1/sqrt(MUL*MUL)
    g_tab[i] = make_float4(g3a * PN, g3b * PN, g3c * PN, 0.0f);
}

// ---------------- edge kernel: scatter T[dst, k, u] += c_k(e) * Ai_src[u] ----------------
__global__ void __launch_bounds__(256)
edge_kernel(const float* __restrict__ pos,
            const int*   __restrict__ esrc,
            const int*   __restrict__ edst,
            const float* __restrict__ shifts,
            const int*   __restrict__ batch,
            const float* __restrict__ cell,
            int E)
{
    int e = blockIdx.x * 256 + threadIdx.x;
    if (e >= E) return;

    int s0 = esrc[e];
    int d0 = edst[e];

    float dx = pos[d0 * 3 + 0] - pos[s0 * 3 + 0];
    float dy = pos[d0 * 3 + 1] - pos[s0 * 3 + 1];
    float dz = pos[d0 * 3 + 2] - pos[s0 * 3 + 2];

    float shx = shifts[e * 3 + 0];
    float shy = shifts[e * 3 + 1];
    float shz = shifts[e * 3 + 2];
    if (shx != 0.0f || shy != 0.0f || shz != 0.0f) {
        const float* c = cell + (size_t)batch[s0] * 9;
        dx += shx * c[0] + shy * c[3] + shz * c[6];
        dy += shx * c[1] + shy * c[4] + shz * c[7];
        dz += shx * c[2] + shy * c[5] + shz * c[8];
    }

    float len  = sqrtf(dx * dx + dy * dy + dz * dz);
    float rinv = 1.0f / fmaxf(len, 1e-8f);
    float nx = dx * rinv, ny = dy * rinv, nz = dz * rinv;

    // gate lookup (linear interp; table exactly flat at the tail so clamping is exact)
    float t  = len * ((float)(TABK - 1) / TABXMAX);
    int   i0 = (int)t;
    i0 = i0 < (TABK - 2) ? i0 : (TABK - 2);
    float fr = t - (float)i0;
    float4 ga = g_tab[i0];
    float4 gb = g_tab[i0 + 1];
    float G0 = ga.x + fr * (gb.x - ga.x);
    float G1 = ga.y + fr * (gb.y - ga.y);
    float G2 = ga.z + fr * (gb.z - ga.z);

    // src node features
    const float4* A4 = (const float4*)g_Ai;
    float4 aL = A4[s0 * 2 + 0], aH = A4[s0 * 2 + 1];

    // 9 coefficients: G0*Y0(=1), G1*Y1[i], G2*Y2[i]
    const float SQ3   = 1.7320508075688772f;
    const float SQ15  = 3.872983346207417f;
    const float SQ5H  = 1.118033988749895f;   // sqrt(5)/2
    const float SQ15H = 1.9364916731037085f;  // sqrt(15)/2
    float c9[9];
    c9[0] = G0;
    c9[1] = G1 * (SQ3 * nx);
    c9[2] = G1 * (SQ3 * ny);
    c9[3] = G1 * (SQ3 * nz);
    c9[4] = G2 * (SQ15 * nx * ny);
    c9[5] = G2 * (SQ15 * ny * nz);
    c9[6] = G2 * (SQ5H * (3.0f * nz * nz - 1.0f));
    c9[7] = G2 * (SQ15 * nx * nz);
    c9[8] = G2 * (SQ15H * (nx * nx - ny * ny));

    float4* T4 = (float4*)(g_T + (size_t)d0 * 72);
#pragma unroll
    for (int k = 0; k < 9; k++) {
        float cc = c9[k];
        atomicAdd(&T4[2 * k + 0], make_float4(cc * aL.x, cc * aL.y, cc * aL.z, cc * aL.w));
        atomicAdd(&T4[2 * k + 1], make_float4(cc * aH.x, cc * aH.y, cc * aH.z, cc * aH.w));
    }
    atomicAdd(&g_cnt[d0], 1u);
}

// ---------------- node pass 2: out[n,l,w,i] = (1/cnt) sum_u T[n,l,u,i] * M[n,l,u,w] ----------------
template <int L>
__global__ void __launch_bounds__(128)
node2_kernel(const float* __restrict__ tpw, float* __restrict__ out, int N)
{
    constexpr int ND   = 2 * L + 1;
    constexpr int PATH = (L == 0) ? 0 : (L == 1) ? 3 : 9;
    constexpr int TOFF = (L == 0) ? 0 : (L == 1) ? 8 : 32;   // k-slot offset *8
    constexpr int OOFF = (L == 0) ? 0 : (L == 1) ? 16 : 64;

    __shared__ float Wsm[1024];   // W_L[u,v,w] : (u*8+v)*16 + w
    for (int i = threadIdx.x; i < 1024; i += 128)
        Wsm[i] = tpw[PATH * 1024 + i];
    __syncthreads();

    int n = blockIdx.x * 128 + threadIdx.x;
    if (n >= N) return;

    const float4* A4 = (const float4*)g_Ai;
    float4 bL = A4[n * 2 + 0], bH = A4[n * 2 + 1];
    float b[8] = {bL.x, bL.y, bL.z, bL.w, bH.x, bH.y, bH.z, bH.w};

    const float* Tn = g_T + (size_t)n * 72 + TOFF;

    float acc[16 * ND];
#pragma unroll
    for (int j = 0; j < 16 * ND; j++) acc[j] = 0.0f;

#pragma unroll
    for (int u = 0; u < 8; u++) {
        // M row: m[w] = sum_v b[v] * W[u,v,w]   (broadcast LDS)
        float m[16];
#pragma unroll
        for (int w = 0; w < 16; w++) m[w] = 0.0f;
#pragma unroll
        for (int v = 0; v < 8; v++) {
            float bv = b[v];
            const float4* w4 = (const float4*)(Wsm + (u * 8 + v) * 16);
#pragma unroll
            for (int q = 0; q < 4; q++) {
                float4 w = w4[q];
                m[q * 4 + 0] += bv * w.x;
                m[q * 4 + 1] += bv * w.y;
                m[q * 4 + 2] += bv * w.z;
                m[q * 4 + 3] += bv * w.w;
            }
        }
        float tu[ND];
#pragma unroll
        for (int i = 0; i < ND; i++) tu[i] = Tn[i * 8 + u];
#pragma unroll
        for (int w = 0; w < 16; w++) {
#pragma unroll
            for (int i = 0; i < ND; i++)
                acc[w * ND + i] += m[w] * tu[i];
        }
    }

    unsigned c = g_cnt[n];
    float inv = 1.0f / (float)(c > 0u ? c : 1u);

    float4* row = (float4*)(out + (size_t)n * 144 + OOFF);
#pragma unroll
    for (int j = 0; j < (16 * ND) / 4; j++) {
        row[j] = make_float4(acc[4 * j + 0] * inv, acc[4 * j + 1] * inv,
                             acc[4 * j + 2] * inv, acc[4 * j + 3] * inv);
    }
}

// ---------------- launch ----------------
extern "C" void kernel_launch(void* const* d_in, const int* in_sizes, int n_in,
                              void* d_out, int out_size)
{
    const float* pos    = (const float*)d_in[0];
    const int*   A      = (const int*)  d_in[1];
    const int*   batch  = (const int*)  d_in[2];
    const int*   esrc   = (const int*)  d_in[3];
    const int*   edst   = (const int*)  d_in[4];
    const float* shifts = (const float*)d_in[5];
    const float* cell   = (const float*)d_in[6];
    const float* embT   = (const float*)d_in[7];
    const float* aw1    = (const float*)d_in[8];
    const float* ab1    = (const float*)d_in[9];
    const float* aw2    = (const float*)d_in[10];
    const float* ab2    = (const float*)d_in[11];
    const float* fw1    = (const float*)d_in[12];
    const float* fb1    = (const float*)d_in[13];
    const float* fw2    = (const float*)d_in[14];
    const float* fb2    = (const float*)d_in[15];
    const float* fw3    = (const float*)d_in[16];
    const float* fb3    = (const float*)d_in[17];
    const float* tpw    = (const float*)d_in[18];

    int N = in_sizes[0] / 3;
    int E = in_sizes[3];
    float* out = (float*)d_out;

    node_kernel<<<(N + 255) / 256, 256>>>(embT, A, aw1, ab1, aw2, ab2, N);
    table_kernel<<<TABK / 256, 256>>>(fw1, fb1, fw2, fb2, fw3, fb3);
    edge_kernel<<<(E + 255) / 256, 256>>>(pos, esrc, edst, shifts, batch, cell, E);
    int nb = (N + 127) / 128;
    node2_kernel<0><<<nb, 128>>>(tpw, out, N);
    node2_kernel<1><<<nb, 128>>>(tpw, out, N);
    node2_kernel<2><<<nb, 128>>>(tpw, out, N);
}

// round 3
// speedup vs baseline: 2.3048x; 1.2910x over previous
#include <cuda_runtime.h>
#include <math.h>

// ---------------- scratch (static, no allocations) ----------------
#define MAXN  65536
#define TABK  16384
#define TABXMAX 16.0f

__device__ float4       g_C4[MAXN * 30];     // C[n][a(10)][12 floats = 3 float4] (9 used + pad)
__device__ unsigned int g_cnt[MAXN];         // per-node edge counts
__device__ float4       g_tab[TABK];         // gates(length) table, PATH_NORM folded
__device__ float        g_P[4800];           // P[l(3)][a_dst(10)][a_src(10)][w(16)]

__device__ __forceinline__ float silu_f(float x) {
    return x / (1.0f + __expf(-x));
}

// ---------------- zero C and cnt ----------------
__global__ void zero_kernel(int N)
{
    int i = blockIdx.x * blockDim.x + threadIdx.x;
    int tot = N * 30;
    if (i < tot) g_C4[i] = make_float4(0.f, 0.f, 0.f, 0.f);
    if (i < N)   g_cnt[i] = 0u;
}

// ---------------- precompute: Ai for 10 atom types, then P[l,ad,as,w] ----------------
__global__ void precompute_kernel(const float* __restrict__ emb_table,
                                  const float* __restrict__ w1, const float* __restrict__ b1,
                                  const float* __restrict__ w2, const float* __restrict__ b2,
                                  const float* __restrict__ tpw)
{
    __shared__ float AiS[10][8];
    int t = threadIdx.x;

    if (t < 10) {
        float e[16];
#pragma unroll
        for (int k = 0; k < 16; k++) e[k] = emb_table[t * 16 + k];
        float h[64];
#pragma unroll
        for (int j = 0; j < 64; j++) {
            float acc = b1[j];
#pragma unroll
            for (int k = 0; k < 16; k++) acc += e[k] * w1[k * 64 + j];
            h[j] = silu_f(acc);
        }
#pragma unroll
        for (int m = 0; m < 8; m++) {
            float acc = b2[m];
#pragma unroll
            for (int j = 0; j < 64; j++) acc += h[j] * w2[j * 8 + m];
            AiS[t][m] = acc;
        }
    }
    __syncthreads();

    // P[l][ad][as][w] = sum_u AiS[as][u] * sum_v AiS[ad][v] * W_l[u,v,w]
    for (int idx = t; idx < 4800; idx += blockDim.x) {
        int w  = idx & 15;
        int as = (idx >> 4) % 10;
        int ad = ((idx >> 4) / 10) % 10;
        int l  = idx / 1600;
        int path = (l == 0) ? 0 : (l == 1) ? 3 : 9;
        const float* W = tpw + path * 1024;
        float acc = 0.0f;
#pragma unroll
        for (int u = 0; u < 8; u++) {
            float mu = 0.0f;
#pragma unroll
            for (int v = 0; v < 8; v++)
                mu += AiS[ad][v] * W[(u * 8 + v) * 16 + w];
            acc += AiS[as][u] * mu;
        }
        g_P[idx] = acc;
    }
}

// ---------------- gate table: gates(length) for paths {0,3,9}, *PATH_NORM ----------------
__global__ void table_kernel(const float* __restrict__ fw1, const float* __restrict__ fb1,
                             const float* __restrict__ fw2, const float* __restrict__ fb2,
                             const float* __restrict__ fw3, const float* __restrict__ fb3)
{
    int i = blockIdx.x * blockDim.x + threadIdx.x;
    if (i >= TABK) return;
    float x = (TABXMAX * (float)i) / (float)(TABK - 1);

    const float step = 5.0f / 17.0f;
    float emb[16];
#pragma unroll
    for (int j = 0; j < 16; j++) {
        float v = 5.0f * (float)(j + 1) / 17.0f;
        float d = (x - v) / step;
        emb[j] = __expf(-d * d) * (4.0f / 1.12f);
    }

    float g1[64];
#pragma unroll
    for (int j = 0; j < 64; j++) {
        float acc = __ldg(fb1 + j);
#pragma unroll
        for (int k = 0; k < 16; k++) acc += emb[k] * __ldg(fw1 + k * 64 + j);
        g1[j] = silu_f(acc);
    }

    float g3a = __ldg(fb3 + 0), g3b = __ldg(fb3 + 3), g3c = __ldg(fb3 + 9);
#pragma unroll
    for (int j = 0; j < 64; j++) {
        float acc = __ldg(fb2 + j);
#pragma unroll
        for (int k = 0; k < 64; k++) acc += g1[k] * __ldg(fw2 + k * 64 + j);
        float s = silu_f(acc);
        g3a += s * __ldg(fw3 + j * 15 + 0);
        g3b += s * __ldg(fw3 + j * 15 + 3);
        g3c += s * __ldg(fw3 + j * 15 + 9);
    }
    const float PN = 0.125f; // 1/sqrt(MUL*MUL)
    g_tab[i] = make_float4(g3a * PN, g3b * PN, g3c * PN, 0.0f);
}

// ---------------- edge kernel: C[dst, A[src], k] += gate_l * Y_l[k] ----------------
__global__ void __launch_bounds__(256)
edge_kernel(const float* __restrict__ pos,
            const int*   __restrict__ esrc,
            const int*   __restrict__ edst,
            const float* __restrict__ shifts,
            const int*   __restrict__ batch,
            const float* __restrict__ cell,
            const int*   __restrict__ A,
            int E)
{
    int e = blockIdx.x * 256 + threadIdx.x;
    if (e >= E) return;

    int s0 = esrc[e];
    int d0 = edst[e];

    float dx = pos[d0 * 3 + 0] - pos[s0 * 3 + 0];
    float dy = pos[d0 * 3 + 1] - pos[s0 * 3 + 1];
    float dz = pos[d0 * 3 + 2] - pos[s0 * 3 + 2];

    float shx = shifts[e * 3 + 0];
    float shy = shifts[e * 3 + 1];
    float shz = shifts[e * 3 + 2];
    if (shx != 0.0f || shy != 0.0f || shz != 0.0f) {
        const float* c = cell + (size_t)batch[s0] * 9;
        dx += shx * c[0] + shy * c[3] + shz * c[6];
        dy += shx * c[1] + shy * c[4] + shz * c[7];
        dz += shx * c[2] + shy * c[5] + shz * c[8];
    }

    float len  = sqrtf(dx * dx + dy * dy + dz * dz);
    float rinv = 1.0f / fmaxf(len, 1e-8f);
    float nx = dx * rinv, ny = dy * rinv, nz = dz * rinv;

    // gate lookup (table exactly flat at the tail, so clamping is exact)
    float t  = len * ((float)(TABK - 1) / TABXMAX);
    int   i0 = (int)t;
    i0 = i0 < (TABK - 2) ? i0 : (TABK - 2);
    float fr = t - (float)i0;
    float4 ga = g_tab[i0];
    float4 gb = g_tab[i0 + 1];
    float G0 = ga.x + fr * (gb.x - ga.x);
    float G1 = ga.y + fr * (gb.y - ga.y);
    float G2 = ga.z + fr * (gb.z - ga.z);

    const float SQ3   = 1.7320508075688772f;
    const float SQ15  = 3.872983346207417f;
    const float SQ5H  = 1.118033988749895f;   // sqrt(5)/2
    const float SQ15H = 1.9364916731037085f;  // sqrt(15)/2

    float4 q0 = make_float4(G0,
                            G1 * (SQ3 * nx),
                            G1 * (SQ3 * ny),
                            G1 * (SQ3 * nz));
    float4 q1 = make_float4(G2 * (SQ15 * nx * ny),
                            G2 * (SQ15 * ny * nz),
                            G2 * (SQ5H * (3.0f * nz * nz - 1.0f)),
                            G2 * (SQ15 * nx * nz));
    float4 q2 = make_float4(G2 * (SQ15H * (nx * nx - ny * ny)), 0.0f, 0.0f, 0.0f);

    int a = A[s0];
    float4* Crow = &g_C4[((size_t)d0 * 10 + a) * 3];
    atomicAdd(&Crow[0], q0);
    atomicAdd(&Crow[1], q1);
    atomicAdd(&Crow[2], q2);
    atomicAdd(&g_cnt[d0], 1u);
}

// ---------------- node output: out[n,l,w,i] = (1/cnt) sum_a C[n,a,(l,i)] * P[A[n],a,l,w] ----------------
template <int L>
__device__ __forceinline__ void node_out_impl(const int* __restrict__ A,
                                              float* __restrict__ out, int N)
{
    constexpr int ND   = 2 * L + 1;
    constexpr int OOFF = (L == 0) ? 0 : (L == 1) ? 16 : 64;

    __shared__ float Psm[1600];  // P[L][ad][as][w]
    for (int i = threadIdx.x; i < 1600; i += 128)
        Psm[i] = g_P[L * 1600 + i];
    __syncthreads();

    int n = blockIdx.x * 128 + threadIdx.x;
    if (n >= N) return;

    int at = A[n];
    const float* Pn = Psm + at * 160;

    float acc[16 * ND];
#pragma unroll
    for (int j = 0; j < 16 * ND; j++) acc[j] = 0.0f;

    const float4* Crow = &g_C4[(size_t)n * 30];

#pragma unroll
    for (int a = 0; a < 10; a++) {
        float cn[ND];
        if (L == 0) {
            float4 q0 = Crow[a * 3 + 0];
            cn[0] = q0.x;
        } else if (L == 1) {
            float4 q0 = Crow[a * 3 + 0];
            cn[0] = q0.y; cn[1] = q0.z; cn[2] = q0.w;
        } else {
            float4 q1 = Crow[a * 3 + 1];
            float4 q2 = Crow[a * 3 + 2];
            cn[0] = q1.x; cn[1] = q1.y; cn[2] = q1.z; cn[3] = q1.w; cn[4] = q2.x;
        }
        const float* Pr = Pn + a * 16;
#pragma unroll
        for (int w = 0; w < 16; w++) {
            float pw = Pr[w];
#pragma unroll
            for (int i = 0; i < ND; i++)
                acc[w * ND + i] += pw * cn[i];
        }
    }

    unsigned c = g_cnt[n];
    float inv = 1.0f / (float)(c > 0u ? c : 1u);

    float4* row = (float4*)(out + (size_t)n * 144 + OOFF);
#pragma unroll
    for (int j = 0; j < (16 * ND) / 4; j++) {
        row[j] = make_float4(acc[4 * j + 0] * inv, acc[4 * j + 1] * inv,
                             acc[4 * j + 2] * inv, acc[4 * j + 3] * inv);
    }
}

__global__ void __launch_bounds__(128)
node_out_kernel(const int* __restrict__ A, float* __restrict__ out, int N)
{
    int l = blockIdx.y;
    if (l == 0)      node_out_impl<0>(A, out, N);
    else if (l == 1) node_out_impl<1>(A, out, N);
    else             node_out_impl<2>(A, out, N);
}

// ---------------- launch ----------------
extern "C" void kernel_launch(void* const* d_in, const int* in_sizes, int n_in,
                              void* d_out, int out_size)
{
    const float* pos    = (const float*)d_in[0];
    const int*   A      = (const int*)  d_in[1];
    const int*   batch  = (const int*)  d_in[2];
    const int*   esrc   = (const int*)  d_in[3];
    const int*   edst   = (const int*)  d_in[4];
    const float* shifts = (const float*)d_in[5];
    const float* cell   = (const float*)d_in[6];
    const float* embT   = (const float*)d_in[7];
    const float* aw1    = (const float*)d_in[8];
    const float* ab1    = (const float*)d_in[9];
    const float* aw2    = (const float*)d_in[10];
    const float* ab2    = (const float*)d_in[11];
    const float* fw1    = (const float*)d_in[12];
    const float* fb1    = (const float*)d_in[13];
    const float* fw2    = (const float*)d_in[14];
    const float* fb2    = (const float*)d_in[15];
    const float* fw3    = (const float*)d_in[16];
    const float* fb3    = (const float*)d_in[17];
    const float* tpw    = (const float*)d_in[18];

    int N = in_sizes[0] / 3;
    int E = in_sizes[3];
    float* out = (float*)d_out;

    zero_kernel<<<(N * 30 + 255) / 256, 256>>>(N);
    precompute_kernel<<<1, 512>>>(embT, aw1, ab1, aw2, ab2, tpw);
    table_kernel<<<TABK / 256, 256>>>(fw1, fb1, fw2, fb2, fw3, fb3);
    edge_kernel<<<(E + 255) / 256, 256>>>(pos, esrc, edst, shifts, batch, cell, A, E);
    dim3 grid((N + 127) / 128, 3);
    node_out_kernel<<<grid, 128>>>(A, out, N);
}

// round 4
// speedup vs baseline: 2.9185x; 1.2663x over previous
#include <cuda_runtime.h>
#include <math.h>

// ---------------- scratch (static, no allocations) ----------------
#define MAXN  65536
#define TABK  4096
#define TABXMAX 16.0f
#define PREB  20          // precompute blocks
#define TABB  (TABK/256)  // table blocks

__device__ float4 g_C4[MAXN * 30];   // C[n][a(10)][3 float4]: 9 coeffs + count in slot2.y
__device__ float4 g_pa[MAXN];        // packed (pos.xyz, A-as-bits)
__device__ float4 g_tab[TABK];       // gates(length) table, PATH_NORM folded
__device__ float  g_P[4800];         // P[l(3)][a_dst(10)][a_src(10)][w(16)]

__device__ __forceinline__ float silu_f(float x) {
    return x / (1.0f + __expf(-x));
}

// ---------------- fused prep: zero C / pack pos+A / gate table / P precompute ----------------
__global__ void __launch_bounds__(256)
prep_kernel(const float* __restrict__ pos, const int* __restrict__ A,
            const float* __restrict__ embT,
            const float* __restrict__ aw1, const float* __restrict__ ab1,
            const float* __restrict__ aw2, const float* __restrict__ ab2,
            const float* __restrict__ fw1, const float* __restrict__ fb1,
            const float* __restrict__ fw2, const float* __restrict__ fb2,
            const float* __restrict__ fw3, const float* __restrict__ fb3,
            const float* __restrict__ tpw,
            int N, int ZB)
{
    int bid = blockIdx.x;
    int tid = threadIdx.x;

    if (bid < ZB) {
        // -------- zero C, pack pos+A --------
        int i  = bid * 256 + tid;
        int nz = N * 30;
        if (i < nz) {
            g_C4[i] = make_float4(0.f, 0.f, 0.f, 0.f);
        } else {
            int n = i - nz;
            if (n < N) {
                g_pa[n] = make_float4(pos[3 * n + 0], pos[3 * n + 1], pos[3 * n + 2],
                                      __int_as_float(A[n]));
            }
        }
        return;
    }

    if (bid < ZB + TABB) {
        // -------- gate table --------
        int i = (bid - ZB) * 256 + tid;
        float x = (TABXMAX * (float)i) / (float)(TABK - 1);

        const float step = 5.0f / 17.0f;
        float emb[16];
#pragma unroll
        for (int j = 0; j < 16; j++) {
            float v = 5.0f * (float)(j + 1) / 17.0f;
            float d = (x - v) / step;
            emb[j] = __expf(-d * d) * (4.0f / 1.12f);
        }

        float g1[64];
#pragma unroll
        for (int j = 0; j < 64; j++) {
            float acc = __ldg(fb1 + j);
#pragma unroll
            for (int k = 0; k < 16; k++) acc += emb[k] * __ldg(fw1 + k * 64 + j);
            g1[j] = silu_f(acc);
        }

        float g3a = __ldg(fb3 + 0), g3b = __ldg(fb3 + 3), g3c = __ldg(fb3 + 9);
#pragma unroll
        for (int j = 0; j < 64; j++) {
            float acc = __ldg(fb2 + j);
#pragma unroll
            for (int k = 0; k < 64; k++) acc += g1[k] * __ldg(fw2 + k * 64 + j);
            float s = silu_f(acc);
            g3a += s * __ldg(fw3 + j * 15 + 0);
            g3b += s * __ldg(fw3 + j * 15 + 3);
            g3c += s * __ldg(fw3 + j * 15 + 9);
        }
        const float PN = 0.125f; // 1/sqrt(MUL*MUL)
        g_tab[i] = make_float4(g3a * PN, g3b * PN, g3c * PN, 0.0f);
        return;
    }

    // -------- P precompute (20 blocks x 240 idx) --------
    {
        __shared__ float AiS[10][8];
        if (tid < 10) {
            float e[16];
#pragma unroll
            for (int k = 0; k < 16; k++) e[k] = embT[tid * 16 + k];
            float h[64];
#pragma unroll
            for (int j = 0; j < 64; j++) {
                float acc = ab1[j];
#pragma unroll
                for (int k = 0; k < 16; k++) acc += e[k] * aw1[k * 64 + j];
                h[j] = silu_f(acc);
            }
#pragma unroll
            for (int m = 0; m < 8; m++) {
                float acc = ab2[m];
#pragma unroll
                for (int j = 0; j < 64; j++) acc += h[j] * aw2[j * 8 + m];
                AiS[tid][m] = acc;
            }
        }
        __syncthreads();

        int pb = bid - ZB - TABB;       // 0..PREB-1
        if (tid < 240) {
            int idx = pb * 240 + tid;   // [0, 4800)
            int w  = idx & 15;
            int as = (idx >> 4) % 10;
            int ad = ((idx >> 4) / 10) % 10;
            int l  = idx / 1600;
            int path = (l == 0) ? 0 : (l == 1) ? 3 : 9;
            const float* W = tpw + path * 1024;
            float acc = 0.0f;
#pragma unroll
            for (int u = 0; u < 8; u++) {
                float mu = 0.0f;
#pragma unroll
                for (int v = 0; v < 8; v++)
                    mu += AiS[ad][v] * W[(u * 8 + v) * 16 + w];
                acc += AiS[as][u] * mu;
            }
            g_P[idx] = acc;
        }
    }
}

// ---------------- edge kernel: C[dst, A[src], k] += gate_l * Y_l[k], count in q2.y ----------------
__global__ void __launch_bounds__(256)
edge_kernel(const int*   __restrict__ esrc,
            const int*   __restrict__ edst,
            const float* __restrict__ shifts,
            const int*   __restrict__ batch,
            const float* __restrict__ cell,
            int E)
{
    int e = blockIdx.x * 256 + threadIdx.x;
    if (e >= E) return;

    int s0 = esrc[e];
    int d0 = edst[e];

    float4 ps = __ldg(&g_pa[s0]);
    float4 pd = __ldg(&g_pa[d0]);

    float dx = pd.x - ps.x;
    float dy = pd.y - ps.y;
    float dz = pd.z - ps.z;

    float shx = shifts[e * 3 + 0];
    float shy = shifts[e * 3 + 1];
    float shz = shifts[e * 3 + 2];
    if (shx != 0.0f || shy != 0.0f || shz != 0.0f) {
        const float* c = cell + (size_t)batch[s0] * 9;
        dx += shx * c[0] + shy * c[3] + shz * c[6];
        dy += shx * c[1] + shy * c[4] + shz * c[7];
        dz += shx * c[2] + shy * c[5] + shz * c[8];
    }

    float len  = sqrtf(dx * dx + dy * dy + dz * dz);
    float rinv = 1.0f / fmaxf(len, 1e-8f);
    float nx = dx * rinv, ny = dy * rinv, nz = dz * rinv;

    // gate lookup (table exactly flat at the tail, so clamping is exact)
    float t  = len * ((float)(TABK - 1) / TABXMAX);
    int   i0 = (int)t;
    i0 = i0 < (TABK - 2) ? i0 : (TABK - 2);
    float fr = t - (float)i0;
    float4 ga = __ldg(&g_tab[i0]);
    float4 gb = __ldg(&g_tab[i0 + 1]);
    float G0 = ga.x + fr * (gb.x - ga.x);
    float G1 = ga.y + fr * (gb.y - ga.y);
    float G2 = ga.z + fr * (gb.z - ga.z);

    const float SQ3   = 1.7320508075688772f;
    const float SQ15  = 3.872983346207417f;
    const float SQ5H  = 1.118033988749895f;   // sqrt(5)/2
    const float SQ15H = 1.9364916731037085f;  // sqrt(15)/2

    float4 q0 = make_float4(G0,
                            G1 * (SQ3 * nx),
                            G1 * (SQ3 * ny),
                            G1 * (SQ3 * nz));
    float4 q1 = make_float4(G2 * (SQ15 * nx * ny),
                            G2 * (SQ15 * ny * nz),
                            G2 * (SQ5H * (3.0f * nz * nz - 1.0f)),
                            G2 * (SQ15 * nx * nz));
    float4 q2 = make_float4(G2 * (SQ15H * (nx * nx - ny * ny)), 1.0f, 0.0f, 0.0f);

    int a = __float_as_int(ps.w);
    float4* Crow = &g_C4[((size_t)d0 * 10 + a) * 3];
    atomicAdd(&Crow[0], q0);
    atomicAdd(&Crow[1], q1);
    atomicAdd(&Crow[2], q2);
}

// ---------------- node output: all three l in one pass ----------------
__global__ void __launch_bounds__(64)
node_out_kernel(float* __restrict__ out, int N)
{
    // Psm[(l*160 + a*16 + w)*10 + at]  -> per-lane `at` indexing is coalesced/conflict-free
    __shared__ float Psm[4800];
    for (int i = threadIdx.x; i < 4800; i += 64) {
        int w  = i & 15;
        int as = (i >> 4) % 10;
        int ad = ((i >> 4) / 10) % 10;
        int l  = i / 1600;
        Psm[(l * 160 + as * 16 + w) * 10 + ad] = g_P[i];
    }
    __syncthreads();

    int n = blockIdx.x * 64 + threadIdx.x;
    if (n >= N) return;

    int at = __float_as_int(__ldg(&g_pa[n]).w);
    const float4* Crow = &g_C4[(size_t)n * 30];

    // count = sum over a of q2.y
    float cnt = 0.0f;
#pragma unroll
    for (int a = 0; a < 10; a++) cnt += Crow[a * 3 + 2].y;
    float inv = 1.0f / fmaxf(cnt, 1.0f);

    float* row = out + (size_t)n * 144;

    // ---- l = 0 ----
    {
        float acc[16];
#pragma unroll
        for (int w = 0; w < 16; w++) acc[w] = 0.0f;
#pragma unroll
        for (int a = 0; a < 10; a++) {
            float c0 = Crow[a * 3 + 0].x;
            const float* Pr = Psm + (0 * 160 + a * 16) * 10 + at;
#pragma unroll
            for (int w = 0; w < 16; w++) acc[w] += Pr[w * 10] * c0;
        }
        float4* r4 = (float4*)row;
#pragma unroll
        for (int j = 0; j < 4; j++)
            r4[j] = make_float4(acc[4*j]*inv, acc[4*j+1]*inv, acc[4*j+2]*inv, acc[4*j+3]*inv);
    }
    // ---- l = 1 ----
    {
        float acc[48];
#pragma unroll
        for (int j = 0; j < 48; j++) acc[j] = 0.0f;
#pragma unroll
        for (int a = 0; a < 10; a++) {
            float4 q0 = Crow[a * 3 + 0];
            float c0 = q0.y, c1 = q0.z, c2 = q0.w;
            const float* Pr = Psm + (1 * 160 + a * 16) * 10 + at;
#pragma unroll
            for (int w = 0; w < 16; w++) {
                float pw = Pr[w * 10];
                acc[w * 3 + 0] += pw * c0;
                acc[w * 3 + 1] += pw * c1;
                acc[w * 3 + 2] += pw * c2;
            }
        }
        float4* r4 = (float4*)(row + 16);
#pragma unroll
        for (int j = 0; j < 12; j++)
            r4[j] = make_float4(acc[4*j]*inv, acc[4*j+1]*inv, acc[4*j+2]*inv, acc[4*j+3]*inv);
    }
    // ---- l = 2 ----
    {
        float acc[80];
#pragma unroll
        for (int j = 0; j < 80; j++) acc[j] = 0.0f;
#pragma unroll
        for (int a = 0; a < 10; a++) {
            float4 q1 = Crow[a * 3 + 1];
            float4 q2 = Crow[a * 3 + 2];
            float c0 = q1.x, c1 = q1.y, c2 = q1.z, c3 = q1.w, c4 = q2.x;
            const float* Pr = Psm + (2 * 160 + a * 16) * 10 + at;
#pragma unroll
            for (int w = 0; w < 16; w++) {
                float pw = Pr[w * 10];
                acc[w * 5 + 0] += pw * c0;
                acc[w * 5 + 1] += pw * c1;
                acc[w * 5 + 2] += pw * c2;
                acc[w * 5 + 3] += pw * c3;
                acc[w * 5 + 4] += pw * c4;
            }
        }
        float4* r4 = (float4*)(row + 64);
#pragma unroll
        for (int j = 0; j < 20; j++)
            r4[j] = make_float4(acc[4*j]*inv, acc[4*j+1]*inv, acc[4*j+2]*inv, acc[4*j+3]*inv);
    }
}

// ---------------- launch ----------------
extern "C" void kernel_launch(void* const* d_in, const int* in_sizes, int n_in,
                              void* d_out, int out_size)
{
    const float* pos    = (const float*)d_in[0];
    const int*   A      = (const int*)  d_in[1];
    const int*   batch  = (const int*)  d_in[2];
    const int*   esrc   = (const int*)  d_in[3];
    const int*   edst   = (const int*)  d_in[4];
    const float* shifts = (const float*)d_in[5];
    const float* cell   = (const float*)d_in[6];
    const float* embT   = (const float*)d_in[7];
    const float* aw1    = (const float*)d_in[8];
    const float* ab1    = (const float*)d_in[9];
    const float* aw2    = (const float*)d_in[10];
    const float* ab2    = (const float*)d_in[11];
    const float* fw1    = (const float*)d_in[12];
    const float* fb1    = (const float*)d_in[13];
    const float* fw2    = (const float*)d_in[14];
    const float* fb2    = (const float*)d_in[15];
    const float* fw3    = (const float*)d_in[16];
    const float* fb3    = (const float*)d_in[17];
    const float* tpw    = (const float*)d_in[18];

    int N = in_sizes[0] / 3;
    int E = in_sizes[3];
    float* out = (float*)d_out;

    int ZB = (N * 31 + 255) / 256;
    prep_kernel<<<ZB + TABB + PREB, 256>>>(pos, A, embT, aw1, ab1, aw2, ab2,
                                           fw1, fb1, fw2, fb2, fw3, fb3, tpw, N, ZB);
    edge_kernel<<<(E + 255) / 256, 256>>>(esrc, edst, shifts, batch, cell, E);
    node_out_kernel<<<(N + 63) / 64, 64>>>(out, N);
}

// round 5
// speedup vs baseline: 5.8173x; 1.9932x over previous
#include <cuda_runtime.h>
#include <math.h>

// ---------------- scratch (static, no allocations) ----------------
#define MAXN  65536
#define TABK  4096
#define TABXMAX 16.0f

__device__ float4 g_C4[MAXN * 30];   // C[n][a(10)][3 float4]: 9 coeffs + count in slot2.y
__device__ float4 g_pa[MAXN];        // packed (pos.xyz, A-as-bits)
__device__ float4 g_tab[TABK];       // gates(length) table, PATH_NORM folded
__device__ float  g_P[4800];         // P[l(3)][a_dst(10)][a_src(10)][w(16)]

__device__ __forceinline__ float silu_f(float x) {
    return x / (1.0f + __expf(-x));
}

// ---------------- k1: zero C, pack pos+A ----------------
__global__ void __launch_bounds__(256)
zero_pack_kernel(const float* __restrict__ pos, const int* __restrict__ A, int N)
{
    int i  = blockIdx.x * 256 + threadIdx.x;
    int nz = N * 30;
    if (i < nz) {
        g_C4[i] = make_float4(0.f, 0.f, 0.f, 0.f);
    } else {
        int n = i - nz;
        if (n < N)
            g_pa[n] = make_float4(pos[3 * n + 0], pos[3 * n + 1], pos[3 * n + 2],
                                  __int_as_float(A[n]));
    }
}

// ---------------- k2: gate table, warp per entry ----------------
__global__ void __launch_bounds__(256)
table_kernel(const float* __restrict__ fw1, const float* __restrict__ fb1,
             const float* __restrict__ fw2, const float* __restrict__ fb2,
             const float* __restrict__ fw3, const float* __restrict__ fb3)
{
    __shared__ float sW1[16 * 64];
    __shared__ float sW2[64 * 64];
    __shared__ float sW3[3 * 64];
    __shared__ float sB1[64], sB2[64];
    __shared__ float sG[8][64];

    int tid = threadIdx.x;
    for (int i = tid; i < 16 * 64; i += 256) sW1[i] = fw1[i];
    for (int i = tid; i < 64 * 64; i += 256) sW2[i] = fw2[i];
    if (tid < 64) {
        sW3[tid]       = fw3[tid * 15 + 0];
        sW3[64 + tid]  = fw3[tid * 15 + 3];
        sW3[128 + tid] = fw3[tid * 15 + 9];
        sB1[tid] = fb1[tid];
        sB2[tid] = fb2[tid];
    }
    __syncthreads();

    int warp = tid >> 5, lane = tid & 31;
    int entry = blockIdx.x * 8 + warp;
    float x = (TABXMAX * (float)entry) / (float)(TABK - 1);

    // emb: lane k<16 holds emb[k]
    float ev = 0.0f;
    if (lane < 16) {
        const float step = 5.0f / 17.0f;
        float v = 5.0f * (float)(lane + 1) / 17.0f;
        float d = (x - v) / step;
        ev = __expf(-d * d) * (4.0f / 1.12f);
    }

    // layer 1: lane owns neurons {lane, lane+32}
    float a0 = sB1[lane], a1 = sB1[lane + 32];
#pragma unroll
    for (int k = 0; k < 16; k++) {
        float e = __shfl_sync(0xffffffffu, ev, k);
        a0 += e * sW1[k * 64 + lane];
        a1 += e * sW1[k * 64 + lane + 32];
    }
    sG[warp][lane]      = silu_f(a0);
    sG[warp][lane + 32] = silu_f(a1);
    __syncwarp();

    // layer 2
    float b0 = sB2[lane], b1 = sB2[lane + 32];
#pragma unroll
    for (int k = 0; k < 64; k++) {
        float g = sG[warp][k];
        b0 += g * sW2[k * 64 + lane];
        b1 += g * sW2[k * 64 + lane + 32];
    }
    float h0 = silu_f(b0), h1 = silu_f(b1);

    // output: 3 gate columns, warp-reduce
    float pa = h0 * sW3[lane]       + h1 * sW3[lane + 32];
    float pb = h0 * sW3[64 + lane]  + h1 * sW3[64 + lane + 32];
    float pc = h0 * sW3[128 + lane] + h1 * sW3[128 + lane + 32];
#pragma unroll
    for (int off = 16; off > 0; off >>= 1) {
        pa += __shfl_xor_sync(0xffffffffu, pa, off);
        pb += __shfl_xor_sync(0xffffffffu, pb, off);
        pc += __shfl_xor_sync(0xffffffffu, pc, off);
    }
    if (lane == 0) {
        const float PN = 0.125f;
        g_tab[entry] = make_float4((pa + __ldg(fb3 + 0)) * PN,
                                   (pb + __ldg(fb3 + 3)) * PN,
                                   (pc + __ldg(fb3 + 9)) * PN, 0.0f);
    }
}

// ---------------- k3: P precompute (20 blocks x 240) ----------------
__global__ void __launch_bounds__(256)
p_kernel(const float* __restrict__ embT,
         const float* __restrict__ aw1, const float* __restrict__ ab1,
         const float* __restrict__ aw2, const float* __restrict__ ab2,
         const float* __restrict__ tpw)
{
    __shared__ float hS[10][64];
    __shared__ float AiS[10][8];
    int tid = threadIdx.x;

    for (int idx = tid; idx < 640; idx += 256) {
        int a = idx >> 6, j = idx & 63;
        float acc = ab1[j];
#pragma unroll
        for (int k = 0; k < 16; k++) acc += embT[a * 16 + k] * aw1[k * 64 + j];
        hS[a][j] = silu_f(acc);
    }
    __syncthreads();
    if (tid < 80) {
        int a = tid / 8, m = tid % 8;
        float acc = ab2[m];
#pragma unroll
        for (int j = 0; j < 64; j++) acc += hS[a][j] * aw2[j * 8 + m];
        AiS[a][m] = acc;
    }
    __syncthreads();

    if (tid < 240) {
        int idx = blockIdx.x * 240 + tid;   // [0, 4800)
        int w  = idx & 15;
        int as = (idx >> 4) % 10;
        int ad = ((idx >> 4) / 10) % 10;
        int l  = idx / 1600;
        int path = (l == 0) ? 0 : (l == 1) ? 3 : 9;
        const float* W = tpw + path * 1024;
        float acc = 0.0f;
#pragma unroll
        for (int u = 0; u < 8; u++) {
            float mu = 0.0f;
#pragma unroll
            for (int v = 0; v < 8; v++)
                mu += AiS[ad][v] * W[(u * 8 + v) * 16 + w];
            acc += AiS[as][u] * mu;
        }
        g_P[idx] = acc;
    }
}

// ---------------- k4: edge scatter ----------------
__global__ void __launch_bounds__(256)
edge_kernel(const int*   __restrict__ esrc,
            const int*   __restrict__ edst,
            const float* __restrict__ shifts,
            const int*   __restrict__ batch,
            const float* __restrict__ cell,
            int E)
{
    int e = blockIdx.x * 256 + threadIdx.x;
    if (e >= E) return;

    int s0 = esrc[e];
    int d0 = edst[e];

    float4 ps = __ldg(&g_pa[s0]);
    float4 pd = __ldg(&g_pa[d0]);

    float dx = pd.x - ps.x;
    float dy = pd.y - ps.y;
    float dz = pd.z - ps.z;

    float shx = shifts[e * 3 + 0];
    float shy = shifts[e * 3 + 1];
    float shz = shifts[e * 3 + 2];
    if (shx != 0.0f || shy != 0.0f || shz != 0.0f) {
        const float* c = cell + (size_t)batch[s0] * 9;
        dx += shx * c[0] + shy * c[3] + shz * c[6];
        dy += shx * c[1] + shy * c[4] + shz * c[7];
        dz += shx * c[2] + shy * c[5] + shz * c[8];
    }

    float len  = sqrtf(dx * dx + dy * dy + dz * dz);
    float rinv = 1.0f / fmaxf(len, 1e-8f);
    float nx = dx * rinv, ny = dy * rinv, nz = dz * rinv;

    float t  = len * ((float)(TABK - 1) / TABXMAX);
    int   i0 = (int)t;
    i0 = i0 < (TABK - 2) ? i0 : (TABK - 2);
    float fr = t - (float)i0;
    float4 ga = __ldg(&g_tab[i0]);
    float4 gb = __ldg(&g_tab[i0 + 1]);
    float G0 = ga.x + fr * (gb.x - ga.x);
    float G1 = ga.y + fr * (gb.y - ga.y);
    float G2 = ga.z + fr * (gb.z - ga.z);

    const float SQ3   = 1.7320508075688772f;
    const float SQ15  = 3.872983346207417f;
    const float SQ5H  = 1.118033988749895f;
    const float SQ15H = 1.9364916731037085f;

    float4 q0 = make_float4(G0,
                            G1 * (SQ3 * nx),
                            G1 * (SQ3 * ny),
                            G1 * (SQ3 * nz));
    float4 q1 = make_float4(G2 * (SQ15 * nx * ny),
                            G2 * (SQ15 * ny * nz),
                            G2 * (SQ5H * (3.0f * nz * nz - 1.0f)),
                            G2 * (SQ15 * nx * nz));
    float4 q2 = make_float4(G2 * (SQ15H * (nx * nx - ny * ny)), 1.0f, 0.0f, 0.0f);

    int a = __float_as_int(ps.w);
    float4* Crow = &g_C4[((size_t)d0 * 10 + a) * 3];
    atomicAdd(&Crow[0], q0);
    atomicAdd(&Crow[1], q1);
    atomicAdd(&Crow[2], q2);
}

// ---------------- k5: node output, all three l ----------------
__global__ void __launch_bounds__(64)
node_out_kernel(float* __restrict__ out, int N)
{
    // Psm[(l*160 + a*16 + w)*10 + at]
    __shared__ float Psm[4800];
    for (int i = threadIdx.x; i < 4800; i += 64) {
        int w  = i & 15;
        int as = (i >> 4) % 10;
        int ad = ((i >> 4) / 10) % 10;
        int l  = i / 1600;
        Psm[(l * 160 + as * 16 + w) * 10 + ad] = g_P[i];
    }
    __syncthreads();

    int n = blockIdx.x * 64 + threadIdx.x;
    if (n >= N) return;

    int at = __float_as_int(__ldg(&g_pa[n]).w);
    const float4* Crow = &g_C4[(size_t)n * 30];

    float cnt = 0.0f;
#pragma unroll
    for (int a = 0; a < 10; a++) cnt += Crow[a * 3 + 2].y;
    float inv = 1.0f / fmaxf(cnt, 1.0f);

    float* row = out + (size_t)n * 144;

    // ---- l = 0 ----
    {
        float acc[16];
#pragma unroll
        for (int w = 0; w < 16; w++) acc[w] = 0.0f;
#pragma unroll
        for (int a = 0; a < 10; a++) {
            float c0 = Crow[a * 3 + 0].x;
            const float* Pr = Psm + (a * 16) * 10 + at;
#pragma unroll
            for (int w = 0; w < 16; w++) acc[w] += Pr[w * 10] * c0;
        }
        float4* r4 = (float4*)row;
#pragma unroll
        for (int j = 0; j < 4; j++)
            r4[j] = make_float4(acc[4*j]*inv, acc[4*j+1]*inv, acc[4*j+2]*inv, acc[4*j+3]*inv);
    }
    // ---- l = 1 ----
    {
        float acc[48];
#pragma unroll
        for (int j = 0; j < 48; j++) acc[j] = 0.0f;
#pragma unroll
        for (int a = 0; a < 10; a++) {
            float4 q0 = Crow[a * 3 + 0];
            float c0 = q0.y, c1 = q0.z, c2 = q0.w;
            const float* Pr = Psm + (160 + a * 16) * 10 + at;
#pragma unroll
            for (int w = 0; w < 16; w++) {
                float pw = Pr[w * 10];
                acc[w * 3 + 0] += pw * c0;
                acc[w * 3 + 1] += pw * c1;
                acc[w * 3 + 2] += pw * c2;
            }
        }
        float4* r4 = (float4*)(row + 16);
#pragma unroll
        for (int j = 0; j < 12; j++)
            r4[j] = make_float4(acc[4*j]*inv, acc[4*j+1]*inv, acc[4*j+2]*inv, acc[4*j+3]*inv);
    }
    // ---- l = 2 ----
    {
        float acc[80];
#pragma unroll
        for (int j = 0; j < 80; j++) acc[j] = 0.0f;
#pragma unroll
        for (int a = 0; a < 10; a++) {
            float4 q1 = Crow[a * 3 + 1];
            float4 q2 = Crow[a * 3 + 2];
            float c0 = q1.x, c1 = q1.y, c2 = q1.z, c3 = q1.w, c4 = q2.x;
            const float* Pr = Psm + (320 + a * 16) * 10 + at;
#pragma unroll
            for (int w = 0; w < 16; w++) {
                float pw = Pr[w * 10];
                acc[w * 5 + 0] += pw * c0;
                acc[w * 5 + 1] += pw * c1;
                acc[w * 5 + 2] += pw * c2;
                acc[w * 5 + 3] += pw * c3;
                acc[w * 5 + 4] += pw * c4;
            }
        }
        float4* r4 = (float4*)(row + 64);
#pragma unroll
        for (int j = 0; j < 20; j++)
            r4[j] = make_float4(acc[4*j]*inv, acc[4*j+1]*inv, acc[4*j+2]*inv, acc[4*j+3]*inv);
    }
}

// ---------------- launch ----------------
extern "C" void kernel_launch(void* const* d_in, const int* in_sizes, int n_in,
                              void* d_out, int out_size)
{
    const float* pos    = (const float*)d_in[0];
    const int*   A      = (const int*)  d_in[1];
    const int*   batch  = (const int*)  d_in[2];
    const int*   esrc   = (const int*)  d_in[3];
    const int*   edst   = (const int*)  d_in[4];
    const float* shifts = (const float*)d_in[5];
    const float* cell   = (const float*)d_in[6];
    const float* embT   = (const float*)d_in[7];
    const float* aw1    = (const float*)d_in[8];
    const float* ab1    = (const float*)d_in[9];
    const float* aw2    = (const float*)d_in[10];
    const float* ab2    = (const float*)d_in[11];
    const float* fw1    = (const float*)d_in[12];
    const float* fb1    = (const float*)d_in[13];
    const float* fw2    = (const float*)d_in[14];
    const float* fb2    = (const float*)d_in[15];
    const float* fw3    = (const float*)d_in[16];
    const float* fb3    = (const float*)d_in[17];
    const float* tpw    = (const float*)d_in[18];

    int N = in_sizes[0] / 3;
    int E = in_sizes[3];
    float* out = (float*)d_out;

    zero_pack_kernel<<<(N * 31 + 255) / 256, 256>>>(pos, A, N);
    table_kernel<<<TABK / 8, 256>>>(fw1, fb1, fw2, fb2, fw3, fb3);
    p_kernel<<<20, 256>>>(embT, aw1, ab1, aw2, ab2, tpw);
    edge_kernel<<<(E + 255) / 256, 256>>>(esrc, edst, shifts, batch, cell, E);
    node_out_kernel<<<(N + 63) / 64, 64>>>(out, N);
}

// round 6
// speedup vs baseline: 6.6377x; 1.1410x over previous
#include <cuda_runtime.h>
#include <math.h>

// ---------------- scratch (static, no allocations) ----------------
#define MAXN  65536
#define TABK  4096
#define TABXMAX 16.0f
#define TABB  (TABK / 8)   // table blocks (8 entries per block, warp each)
#define PREB  20           // p-precompute blocks

__device__ float4 g_C4[MAXN * 30];   // C[n][a(10)][3 float4]: 9 coeffs + count in slot2.y
__device__ float4 g_pa[MAXN];        // packed (pos.xyz, A-as-bits)
__device__ float4 g_tab[TABK];       // gates(length) table, PATH_NORM folded
__device__ float  g_P[4800];         // P[l(3)][a_dst(10)][a_src(10)][w(16)]

__device__ __forceinline__ float silu_f(float x) {
    return x / (1.0f + __expf(-x));
}

struct TableSmem {
    float sW1[16 * 64];
    float sW2[64 * 64];
    float sW3[3 * 64];
    float sB1[64], sB2[64];
    float sG[8][64];
};
struct PSmem {
    float hS[10][64];
    float AiS[10][8];
};

// ---------------- fused prep: all-parallel bodies (zero/pack | table | P) ----------------
__global__ void __launch_bounds__(256)
prep_kernel(const float* __restrict__ pos, const int* __restrict__ A,
            const float* __restrict__ embT,
            const float* __restrict__ aw1, const float* __restrict__ ab1,
            const float* __restrict__ aw2, const float* __restrict__ ab2,
            const float* __restrict__ fw1, const float* __restrict__ fb1,
            const float* __restrict__ fw2, const float* __restrict__ fb2,
            const float* __restrict__ fw3, const float* __restrict__ fb3,
            const float* __restrict__ tpw,
            int N, int ZB)
{
    __shared__ __align__(16) char smem_raw[sizeof(TableSmem)];
    int bid = blockIdx.x;
    int tid = threadIdx.x;

    if (bid < ZB) {
        // -------- zero C, pack pos+A --------
        int i  = bid * 256 + tid;
        int nz = N * 30;
        if (i < nz) {
            g_C4[i] = make_float4(0.f, 0.f, 0.f, 0.f);
        } else {
            int n = i - nz;
            if (n < N)
                g_pa[n] = make_float4(pos[3 * n + 0], pos[3 * n + 1], pos[3 * n + 2],
                                      __int_as_float(A[n]));
        }
        return;
    }

    if (bid < ZB + TABB) {
        // -------- gate table, warp per entry --------
        TableSmem& S = *reinterpret_cast<TableSmem*>(smem_raw);
        for (int i = tid; i < 16 * 64; i += 256) S.sW1[i] = fw1[i];
        for (int i = tid; i < 64 * 64; i += 256) S.sW2[i] = fw2[i];
        if (tid < 64) {
            S.sW3[tid]       = fw3[tid * 15 + 0];
            S.sW3[64 + tid]  = fw3[tid * 15 + 3];
            S.sW3[128 + tid] = fw3[tid * 15 + 9];
            S.sB1[tid] = fb1[tid];
            S.sB2[tid] = fb2[tid];
        }
        __syncthreads();

        int warp = tid >> 5, lane = tid & 31;
        int entry = (bid - ZB) * 8 + warp;
        float x = (TABXMAX * (float)entry) / (float)(TABK - 1);

        float ev = 0.0f;
        if (lane < 16) {
            const float step = 5.0f / 17.0f;
            float v = 5.0f * (float)(lane + 1) / 17.0f;
            float d = (x - v) / step;
            ev = __expf(-d * d) * (4.0f / 1.12f);
        }

        float a0 = S.sB1[lane], a1 = S.sB1[lane + 32];
#pragma unroll
        for (int k = 0; k < 16; k++) {
            float e = __shfl_sync(0xffffffffu, ev, k);
            a0 += e * S.sW1[k * 64 + lane];
            a1 += e * S.sW1[k * 64 + lane + 32];
        }
        S.sG[warp][lane]      = silu_f(a0);
        S.sG[warp][lane + 32] = silu_f(a1);
        __syncwarp();

        float b0 = S.sB2[lane], b1 = S.sB2[lane + 32];
#pragma unroll
        for (int k = 0; k < 64; k++) {
            float g = S.sG[warp][k];
            b0 += g * S.sW2[k * 64 + lane];
            b1 += g * S.sW2[k * 64 + lane + 32];
        }
        float h0 = silu_f(b0), h1 = silu_f(b1);

        float pa = h0 * S.sW3[lane]       + h1 * S.sW3[lane + 32];
        float pb = h0 * S.sW3[64 + lane]  + h1 * S.sW3[64 + lane + 32];
        float pc = h0 * S.sW3[128 + lane] + h1 * S.sW3[128 + lane + 32];
#pragma unroll
        for (int off = 16; off > 0; off >>= 1) {
            pa += __shfl_xor_sync(0xffffffffu, pa, off);
            pb += __shfl_xor_sync(0xffffffffu, pb, off);
            pc += __shfl_xor_sync(0xffffffffu, pc, off);
        }
        if (lane == 0) {
            const float PN = 0.125f;
            g_tab[entry] = make_float4((pa + __ldg(fb3 + 0)) * PN,
                                       (pb + __ldg(fb3 + 3)) * PN,
                                       (pc + __ldg(fb3 + 9)) * PN, 0.0f);
        }
        return;
    }

    // -------- P precompute (PREB blocks x 240 entries) --------
    {
        PSmem& S = *reinterpret_cast<PSmem*>(smem_raw);
        for (int idx = tid; idx < 640; idx += 256) {
            int a = idx >> 6, j = idx & 63;
            float acc = ab1[j];
#pragma unroll
            for (int k = 0; k < 16; k++) acc += embT[a * 16 + k] * aw1[k * 64 + j];
            S.hS[a][j] = silu_f(acc);
        }
        __syncthreads();
        if (tid < 80) {
            int a = tid / 8, m = tid % 8;
            float acc = ab2[m];
#pragma unroll
            for (int j = 0; j < 64; j++) acc += S.hS[a][j] * aw2[j * 8 + m];
            S.AiS[a][m] = acc;
        }
        __syncthreads();

        if (tid < 240) {
            int idx = (bid - ZB - TABB) * 240 + tid;   // [0, 4800)
            int w  = idx & 15;
            int as = (idx >> 4) % 10;
            int ad = ((idx >> 4) / 10) % 10;
            int l  = idx / 1600;
            int path = (l == 0) ? 0 : (l == 1) ? 3 : 9;
            const float* W = tpw + path * 1024;
            float acc = 0.0f;
#pragma unroll
            for (int u = 0; u < 8; u++) {
                float mu = 0.0f;
#pragma unroll
                for (int v = 0; v < 8; v++)
                    mu += S.AiS[ad][v] * W[(u * 8 + v) * 16 + w];
                acc += S.AiS[as][u] * mu;
            }
            g_P[idx] = acc;
        }
    }
}

// ---------------- edge scatter ----------------
__global__ void __launch_bounds__(256)
edge_kernel(const int*   __restrict__ esrc,
            const int*   __restrict__ edst,
            const float* __restrict__ shifts,
            const int*   __restrict__ batch,
            const float* __restrict__ cell,
            int E)
{
    int e = blockIdx.x * 256 + threadIdx.x;
    if (e >= E) return;

    int s0 = esrc[e];
    int d0 = edst[e];

    float4 ps = __ldg(&g_pa[s0]);
    float4 pd = __ldg(&g_pa[d0]);

    float dx = pd.x - ps.x;
    float dy = pd.y - ps.y;
    float dz = pd.z - ps.z;

    float shx = shifts[e * 3 + 0];
    float shy = shifts[e * 3 + 1];
    float shz = shifts[e * 3 + 2];
    if (shx != 0.0f || shy != 0.0f || shz != 0.0f) {
        const float* c = cell + (size_t)batch[s0] * 9;
        dx += shx * c[0] + shy * c[3] + shz * c[6];
        dy += shx * c[1] + shy * c[4] + shz * c[7];
        dz += shx * c[2] + shy * c[5] + shz * c[8];
    }

    float len  = sqrtf(dx * dx + dy * dy + dz * dz);
    float rinv = 1.0f / fmaxf(len, 1e-8f);
    float nx = dx * rinv, ny = dy * rinv, nz = dz * rinv;

    float t  = len * ((float)(TABK - 1) / TABXMAX);
    int   i0 = (int)t;
    i0 = i0 < (TABK - 2) ? i0 : (TABK - 2);
    float fr = t - (float)i0;
    float4 ga = __ldg(&g_tab[i0]);
    float4 gb = __ldg(&g_tab[i0 + 1]);
    float G0 = ga.x + fr * (gb.x - ga.x);
    float G1 = ga.y + fr * (gb.y - ga.y);
    float G2 = ga.z + fr * (gb.z - ga.z);

    const float SQ3   = 1.7320508075688772f;
    const float SQ15  = 3.872983346207417f;
    const float SQ5H  = 1.118033988749895f;
    const float SQ15H = 1.9364916731037085f;

    float4 q0 = make_float4(G0,
                            G1 * (SQ3 * nx),
                            G1 * (SQ3 * ny),
                            G1 * (SQ3 * nz));
    float4 q1 = make_float4(G2 * (SQ15 * nx * ny),
                            G2 * (SQ15 * ny * nz),
                            G2 * (SQ5H * (3.0f * nz * nz - 1.0f)),
                            G2 * (SQ15 * nx * nz));
    float4 q2 = make_float4(G2 * (SQ15H * (nx * nx - ny * ny)), 1.0f, 0.0f, 0.0f);

    int a = __float_as_int(ps.w);
    float4* Crow = &g_C4[((size_t)d0 * 10 + a) * 3];
    atomicAdd(&Crow[0], q0);
    atomicAdd(&Crow[1], q1);
    atomicAdd(&Crow[2], q2);
}

// ---------------- node output: 2 threads per node (w-halves), all three l ----------------
__global__ void __launch_bounds__(128)
node_out_kernel(float* __restrict__ out, int N)
{
    // Psm[(l*160 + a*16 + w)*10 + at]
    __shared__ float Psm[4800];
    for (int i = threadIdx.x; i < 4800; i += 128) {
        int w  = i & 15;
        int as = (i >> 4) % 10;
        int ad = ((i >> 4) / 10) % 10;
        int l  = i / 1600;
        Psm[(l * 160 + as * 16 + w) * 10 + ad] = g_P[i];
    }
    __syncthreads();

    int t = blockIdx.x * 128 + threadIdx.x;
    int n = t >> 1;
    int q = t & 1;           // w-half: w in [8q, 8q+8)
    if (n >= N) return;

    int at = __float_as_int(__ldg(&g_pa[n]).w);
    const float4* Crow = &g_C4[(size_t)n * 30];
    int wb = 8 * q;

    float acc0[8], acc1[24], acc2[40];
#pragma unroll
    for (int j = 0; j < 8; j++)  acc0[j] = 0.0f;
#pragma unroll
    for (int j = 0; j < 24; j++) acc1[j] = 0.0f;
#pragma unroll
    for (int j = 0; j < 40; j++) acc2[j] = 0.0f;

    float cnt = 0.0f;

#pragma unroll
    for (int a = 0; a < 10; a++) {
        float4 c0 = Crow[a * 3 + 0];
        float4 c1 = Crow[a * 3 + 1];
        float4 c2 = Crow[a * 3 + 2];
        cnt += c2.y;

        const float* P0 = Psm + (a * 16 + wb) * 10 + at;
        const float* P1 = Psm + (160 + a * 16 + wb) * 10 + at;
        const float* P2 = Psm + (320 + a * 16 + wb) * 10 + at;
#pragma unroll
        for (int w = 0; w < 8; w++) {
            float p0 = P0[w * 10];
            float p1 = P1[w * 10];
            float p2 = P2[w * 10];
            acc0[w] += p0 * c0.x;
            acc1[w * 3 + 0] += p1 * c0.y;
            acc1[w * 3 + 1] += p1 * c0.z;
            acc1[w * 3 + 2] += p1 * c0.w;
            acc2[w * 5 + 0] += p2 * c1.x;
            acc2[w * 5 + 1] += p2 * c1.y;
            acc2[w * 5 + 2] += p2 * c1.z;
            acc2[w * 5 + 3] += p2 * c1.w;
            acc2[w * 5 + 4] += p2 * c2.x;
        }
    }

    float inv = 1.0f / fmaxf(cnt, 1.0f);
    float* row = out + (size_t)n * 144;

    // l0: floats [8q, 8q+8)  -> 2 aligned float4
    {
        float4* r4 = (float4*)(row) + 2 * q;
#pragma unroll
        for (int j = 0; j < 2; j++)
            r4[j] = make_float4(acc0[4*j]*inv, acc0[4*j+1]*inv, acc0[4*j+2]*inv, acc0[4*j+3]*inv);
    }
    // l1: floats [16+24q, +24) -> 6 aligned float4
    {
        float4* r4 = (float4*)(row + 16 + 24 * q);
#pragma unroll
        for (int j = 0; j < 6; j++)
            r4[j] = make_float4(acc1[4*j]*inv, acc1[4*j+1]*inv, acc1[4*j+2]*inv, acc1[4*j+3]*inv);
    }
    // l2: floats [64+40q, +40) -> 10 aligned float4
    {
        float4* r4 = (float4*)(row + 64 + 40 * q);
#pragma unroll
        for (int j = 0; j < 10; j++)
            r4[j] = make_float4(acc2[4*j]*inv, acc2[4*j+1]*inv, acc2[4*j+2]*inv, acc2[4*j+3]*inv);
    }
}

// ---------------- launch ----------------
extern "C" void kernel_launch(void* const* d_in, const int* in_sizes, int n_in,
                              void* d_out, int out_size)
{
    const float* pos    = (const float*)d_in[0];
    const int*   A      = (const int*)  d_in[1];
    const int*   batch  = (const int*)  d_in[2];
    const int*   esrc   = (const int*)  d_in[3];
    const int*   edst   = (const int*)  d_in[4];
    const float* shifts = (const float*)d_in[5];
    const float* cell   = (const float*)d_in[6];
    const float* embT   = (const float*)d_in[7];
    const float* aw1    = (const float*)d_in[8];
    const float* ab1    = (const float*)d_in[9];
    const float* aw2    = (const float*)d_in[10];
    const float* ab2    = (const float*)d_in[11];
    const float* fw1    = (const float*)d_in[12];
    const float* fb1    = (const float*)d_in[13];
    const float* fw2    = (const float*)d_in[14];
    const float* fb2    = (const float*)d_in[15];
    const float* fw3    = (const float*)d_in[16];
    const float* fb3    = (const float*)d_in[17];
    const float* tpw    = (const float*)d_in[18];

    int N = in_sizes[0] / 3;
    int E = in_sizes[3];
    float* out = (float*)d_out;

    int ZB = (N * 31 + 255) / 256;
    prep_kernel<<<ZB + TABB + PREB, 256>>>(pos, A, embT, aw1, ab1, aw2, ab2,
                                           fw1, fb1, fw2, fb2, fw3, fb3, tpw, N, ZB);
    edge_kernel<<<(E + 255) / 256, 256>>>(esrc, edst, shifts, batch, cell, E);
    node_out_kernel<<<(2 * N + 127) / 128, 128>>>(out, N);
}